// round 10
// baseline (speedup 1.0000x reference)
#include <cuda_runtime.h>
#include <cstdint>

typedef unsigned long long u64;

// eps = jax.random.normal(jax.random.key(42), (4,4)) replicated on device
// (threefry2x32, partitionable path: bits = x0 ^ x1 of threefry(key,(0,idx))).
__device__ float d_eps[16];

__device__ __forceinline__ unsigned rotl32(unsigned x, int r) {
    return (x << r) | (x >> (32 - r));
}

__global__ void eps_kernel() {
    int i = threadIdx.x;
    if (i >= 16) return;
    const unsigned k0 = 0u, k1 = 42u;
    const unsigned k2 = k0 ^ k1 ^ 0x1BD11BDAu;
    unsigned x0 = 0u + k0;           // counts_hi = 0 (idx < 2^32)
    unsigned x1 = (unsigned)i + k1;  // counts_lo = flat index
#define TF4(rA, rB, rC, rD)                              \
    x0 += x1; x1 = rotl32(x1, rA); x1 ^= x0;             \
    x0 += x1; x1 = rotl32(x1, rB); x1 ^= x0;             \
    x0 += x1; x1 = rotl32(x1, rC); x1 ^= x0;             \
    x0 += x1; x1 = rotl32(x1, rD); x1 ^= x0;
    TF4(13, 15, 26, 6)  x0 += k1; x1 += k2 + 1u;
    TF4(17, 29, 16, 24) x0 += k2; x1 += k0 + 2u;
    TF4(13, 15, 26, 6)  x0 += k0; x1 += k1 + 3u;
    TF4(17, 29, 16, 24) x0 += k1; x1 += k2 + 4u;
    TF4(13, 15, 26, 6)  x0 += k2; x1 += k0 + 5u;
#undef TF4
    unsigned bits = x0 ^ x1;
    float f = __uint_as_float((bits >> 9) | 0x3f800000u) - 1.0f;
    const float lo = -0.99999994f;
    float u = f * (1.0f - lo) + lo;
    u = fmaxf(lo, u);
    d_eps[i] = 1.41421356f * erfinvf(u);
}

// ---- packed f32x2 helpers ----
__device__ __forceinline__ void upk2(u64 v, float& a, float& b) {
    asm("mov.b64 {%0, %1}, %2;" : "=f"(a), "=f"(b) : "l"(v));
}
__device__ __forceinline__ u64 fma2(u64 a, u64 b, u64 c) {
    u64 r; asm("fma.rn.f32x2 %0, %1, %2, %3;" : "=l"(r) : "l"(a), "l"(b), "l"(c));
    return r;
}
__device__ __forceinline__ u64 dup2(float v) {
    u64 r; asm("mov.b64 %0, {%1, %1};" : "=l"(r) : "f"(v)); return r;
}

// j-packed scheme: FFMA2 lanes hold adjacent OUTPUT channels (h_2j, h_2j+1);
// weight operands are contiguous native fp32 pairs. Two batch elements per
// thread share every weight load: one LDS.128 (4 weights) feeds 4 FFMA2.
// Block 128 / min 3 CTAs caps regs at ~170 -> 12 warps/SM (was 8 at 254 regs).
__global__ __launch_bounds__(128, 3) void scm_kernel(
    const float* __restrict__ z,
    const float* __restrict__ W1, const float* __restrict__ b1,
    const float* __restrict__ W2, const float* __restrict__ b2,
    const float* __restrict__ W3, const float* __restrict__ b3,
    const int* __restrict__ mask,
    float* __restrict__ out, int nPairs)
{
    __shared__ __align__(16) float sW1[4][16][32];  // pre-masked per column i
    __shared__ __align__(16) float sW2[32][32];
    __shared__ __align__(16) float sW3[32][4];
    __shared__ __align__(16) float sB1[32], sB2[32], sB3e[4][4];
    __shared__ int sCond[4];

    const int tid = threadIdx.x;
    for (int idx = tid; idx < 4 * 16 * 32; idx += blockDim.x) {
        int i = idx >> 9, rem = idx & 511, k = rem >> 5, j = rem & 31;
        // masked[i,b,l,f] = z[b,l,f] * mask[f,i], k = l*4+f -> f = k&3
        float m = (float)mask[(k & 3) * 4 + i];
        sW1[i][k][j] = W1[k * 32 + j] * m;
    }
    for (int idx = tid; idx < 1024; idx += blockDim.x)
        sW2[idx >> 5][idx & 31] = W2[idx];
    for (int idx = tid; idx < 128; idx += blockDim.x)
        sW3[idx >> 2][idx & 3] = W3[idx];
    if (tid < 32) { sB1[tid] = b1[tid]; sB2[tid] = b2[tid]; }
    if (tid < 16) sB3e[tid >> 2][tid & 3] = b3[tid & 3] + d_eps[tid];
    if (tid < 4) {
        sCond[tid] = (mask[tid] == 1) | (mask[4 + tid] == 1) |
                     (mask[8 + tid] == 1) | (mask[12 + tid] == 1);
    }
    __syncthreads();

    const int t = blockIdx.x * blockDim.x + tid;
    if (t >= nPairs) return;

    // elem A = 2t, elem B = 2t+1
    const float4* zp = (const float4*)z + (size_t)t * 8;
    float xA[16], xB[16];
#pragma unroll
    for (int r = 0; r < 4; r++) {
        float4 a = zp[r], b = zp[4 + r];
        xA[r * 4 + 0] = a.x; xA[r * 4 + 1] = a.y;
        xA[r * 4 + 2] = a.z; xA[r * 4 + 3] = a.w;
        xB[r * 4 + 0] = b.x; xB[r * 4 + 1] = b.y;
        xB[r * 4 + 2] = b.z; xB[r * 4 + 3] = b.w;
    }

    float4* op = (float4*)out + (size_t)t * 8;
    const ulonglong2* b1q = (const ulonglong2*)sB1;  // 128-bit bias init
    const ulonglong2* b2q = (const ulonglong2*)sB2;

#pragma unroll 1   // one column body at a time (I$)
    for (int i = 0; i < 4; i++) {
        if (sCond[i]) {
            // ---- layer 1: 16 -> 32, h1[p] = (h_2p, h_2p+1) ----
            u64 h1A[16], h1B[16];
#pragma unroll
            for (int q = 0; q < 8; q++) {
                ulonglong2 b = b1q[q];
                h1A[2 * q] = b.x; h1A[2 * q + 1] = b.y;
                h1B[2 * q] = b.x; h1B[2 * q + 1] = b.y;
            }
#pragma unroll
            for (int k = 0; k < 16; k++) {
                u64 xa = dup2(xA[k]), xb = dup2(xB[k]);
                const ulonglong2* wr = (const ulonglong2*)sW1[i][k];
#pragma unroll
                for (int q = 0; q < 8; q++) {
                    ulonglong2 w = wr[q];
                    h1A[2 * q]     = fma2(xa, w.x, h1A[2 * q]);
                    h1A[2 * q + 1] = fma2(xa, w.y, h1A[2 * q + 1]);
                    h1B[2 * q]     = fma2(xb, w.x, h1B[2 * q]);
                    h1B[2 * q + 1] = fma2(xb, w.y, h1B[2 * q + 1]);
                }
            }
            // relu + unpack to scalars (unpack is register aliasing, free)
            float hA[32], hB[32];
#pragma unroll
            for (int p = 0; p < 16; p++) {
                float la, ha, lb, hb;
                upk2(h1A[p], la, ha); upk2(h1B[p], lb, hb);
                hA[2 * p] = fmaxf(la, 0.0f); hA[2 * p + 1] = fmaxf(ha, 0.0f);
                hB[2 * p] = fmaxf(lb, 0.0f); hB[2 * p + 1] = fmaxf(hb, 0.0f);
            }

            // ---- layer 2: 32 -> 32 ----
            u64 h2A[16], h2B[16];
#pragma unroll
            for (int q = 0; q < 8; q++) {
                ulonglong2 b = b2q[q];
                h2A[2 * q] = b.x; h2A[2 * q + 1] = b.y;
                h2B[2 * q] = b.x; h2B[2 * q + 1] = b.y;
            }
#pragma unroll
            for (int k = 0; k < 32; k++) {
                u64 aa = dup2(hA[k]), ab = dup2(hB[k]);
                const ulonglong2* wr = (const ulonglong2*)sW2[k];
#pragma unroll
                for (int q = 0; q < 8; q++) {
                    ulonglong2 w = wr[q];
                    h2A[2 * q]     = fma2(aa, w.x, h2A[2 * q]);
                    h2A[2 * q + 1] = fma2(aa, w.y, h2A[2 * q + 1]);
                    h2B[2 * q]     = fma2(ab, w.x, h2B[2 * q]);
                    h2B[2 * q + 1] = fma2(ab, w.y, h2B[2 * q + 1]);
                }
            }
#pragma unroll
            for (int p = 0; p < 16; p++) {
                float la, ha, lb, hb;
                upk2(h2A[p], la, ha); upk2(h2B[p], lb, hb);
                hA[2 * p] = fmaxf(la, 0.0f); hA[2 * p + 1] = fmaxf(ha, 0.0f);
                hB[2 * p] = fmaxf(lb, 0.0f); hB[2 * p + 1] = fmaxf(hb, 0.0f);
            }

            // ---- layer 3: 32 -> 4 (+ bias + eps) ----
            const ulonglong2* b3q = (const ulonglong2*)sB3e[i];
            ulonglong2 b3v = b3q[0];
            u64 oA0 = b3v.x, oA1 = b3v.y, oB0 = b3v.x, oB1 = b3v.y;
#pragma unroll
            for (int k = 0; k < 32; k++) {
                u64 aa = dup2(hA[k]), ab = dup2(hB[k]);
                ulonglong2 w = *(const ulonglong2*)sW3[k];
                oA0 = fma2(aa, w.x, oA0);
                oA1 = fma2(aa, w.y, oA1);
                oB0 = fma2(ab, w.x, oB0);
                oB1 = fma2(ab, w.y, oB1);
            }
            float a0, a1, a2, a3, c0, c1, c2, c3;
            upk2(oA0, a0, a1); upk2(oA1, a2, a3);
            upk2(oB0, c0, c1); upk2(oB1, c2, c3);
            op[i]     = make_float4(a0, a1, a2, a3);
            op[4 + i] = make_float4(c0, c1, c2, c3);
        } else {
            // passthrough: out[b, i, :] = z[b, i, :]
            op[i]     = make_float4(xA[4 * i], xA[4 * i + 1],
                                    xA[4 * i + 2], xA[4 * i + 3]);
            op[4 + i] = make_float4(xB[4 * i], xB[4 * i + 1],
                                    xB[4 * i + 2], xB[4 * i + 3]);
        }
    }
}

extern "C" void kernel_launch(void* const* d_in, const int* in_sizes, int n_in,
                              void* d_out, int out_size) {
    // metadata order: z, z_int, W1, b1, W2, b2, W3, b3, mask, I
    const float* z  = (const float*)d_in[0];
    const float* W1 = (const float*)d_in[2];
    const float* b1 = (const float*)d_in[3];
    const float* W2 = (const float*)d_in[4];
    const float* b2 = (const float*)d_in[5];
    const float* W3 = (const float*)d_in[6];
    const float* b3 = (const float*)d_in[7];
    const int* mask = (const int*)d_in[8];
    float* out = (float*)d_out;

    int B = in_sizes[0] / 16;   // z is [B, 4, 4]
    int nPairs = B / 2;
    eps_kernel<<<1, 16>>>();
    const int threads = 128;
    int blocks = (nPairs + threads - 1) / threads;
    scm_kernel<<<blocks, threads>>>(z, W1, b1, W2, b2, W3, b3, mask, out, nPairs);
}

// round 13
// speedup vs baseline: 1.0650x; 1.0650x over previous
#include <cuda_runtime.h>
#include <cstdint>

typedef unsigned long long u64;

// eps = jax.random.normal(jax.random.key(42), (4,4)) replicated on device
// (threefry2x32, partitionable path: bits = x0 ^ x1 of threefry(key,(0,idx))).
__device__ float d_eps[16];

__device__ __forceinline__ unsigned rotl32(unsigned x, int r) {
    return (x << r) | (x >> (32 - r));
}

__global__ void eps_kernel() {
    int i = threadIdx.x;
    if (i >= 16) return;
    const unsigned k0 = 0u, k1 = 42u;
    const unsigned k2 = k0 ^ k1 ^ 0x1BD11BDAu;
    unsigned x0 = 0u + k0;           // counts_hi = 0 (idx < 2^32)
    unsigned x1 = (unsigned)i + k1;  // counts_lo = flat index
#define TF4(rA, rB, rC, rD)                              \
    x0 += x1; x1 = rotl32(x1, rA); x1 ^= x0;             \
    x0 += x1; x1 = rotl32(x1, rB); x1 ^= x0;             \
    x0 += x1; x1 = rotl32(x1, rC); x1 ^= x0;             \
    x0 += x1; x1 = rotl32(x1, rD); x1 ^= x0;
    TF4(13, 15, 26, 6)  x0 += k1; x1 += k2 + 1u;
    TF4(17, 29, 16, 24) x0 += k2; x1 += k0 + 2u;
    TF4(13, 15, 26, 6)  x0 += k0; x1 += k1 + 3u;
    TF4(17, 29, 16, 24) x0 += k1; x1 += k2 + 4u;
    TF4(13, 15, 26, 6)  x0 += k2; x1 += k0 + 5u;
#undef TF4
    unsigned bits = x0 ^ x1;
    float f = __uint_as_float((bits >> 9) | 0x3f800000u) - 1.0f;
    const float lo = -0.99999994f;
    float u = f * (1.0f - lo) + lo;
    u = fmaxf(lo, u);
    d_eps[i] = 1.41421356f * erfinvf(u);
}

// ---- packed f32x2 helpers ----
__device__ __forceinline__ void upk2(u64 v, float& a, float& b) {
    asm("mov.b64 {%0, %1}, %2;" : "=f"(a), "=f"(b) : "l"(v));
}
__device__ __forceinline__ u64 fma2(u64 a, u64 b, u64 c) {
    u64 r; asm("fma.rn.f32x2 %0, %1, %2, %3;" : "=l"(r) : "l"(a), "l"(b), "l"(c));
    return r;
}
__device__ __forceinline__ u64 dup2(float v) {
    u64 r; asm("mov.b64 %0, {%1, %1};" : "=l"(r) : "f"(v)); return r;
}
// Volatile vector load: blocks ptxas from CSE-hoisting z reloads out of the
// column loop (which would re-extend x liveness and respill).
__device__ __forceinline__ float4 ldg128v(const float4* p) {
    float4 v;
    asm volatile("ld.global.v4.f32 {%0,%1,%2,%3}, [%4];"
                 : "=f"(v.x), "=f"(v.y), "=f"(v.z), "=f"(v.w) : "l"(p));
    return v;
}

// j-packed scheme: FFMA2 lanes hold adjacent OUTPUT channels (h_2j, h_2j+1);
// weight operands are contiguous native fp32 pairs. Two batch elements per
// thread share every weight load: one LDS.128 (4 weights) feeds 4 FFMA2.
// z is RELOADED per column body (L1-resident) so x is not live across the
// column loop -> live set ~150 regs, fits the 170-reg/12-warp budget w/o spills.
__global__ __launch_bounds__(128, 3) void scm_kernel(
    const float* __restrict__ z,
    const float* __restrict__ W1, const float* __restrict__ b1,
    const float* __restrict__ W2, const float* __restrict__ b2,
    const float* __restrict__ W3, const float* __restrict__ b3,
    const int* __restrict__ mask,
    float* __restrict__ out, int nPairs)
{
    __shared__ __align__(16) float sW1[4][16][32];  // pre-masked per column i
    __shared__ __align__(16) float sW2[32][32];
    __shared__ __align__(16) float sW3[32][4];
    __shared__ __align__(16) float sB1[32], sB2[32], sB3e[4][4];
    __shared__ int sCond[4];

    const int tid = threadIdx.x;
    for (int idx = tid; idx < 4 * 16 * 32; idx += blockDim.x) {
        int i = idx >> 9, rem = idx & 511, k = rem >> 5, j = rem & 31;
        // masked[i,b,l,f] = z[b,l,f] * mask[f,i], k = l*4+f -> f = k&3
        float m = (float)mask[(k & 3) * 4 + i];
        sW1[i][k][j] = W1[k * 32 + j] * m;
    }
    for (int idx = tid; idx < 1024; idx += blockDim.x)
        sW2[idx >> 5][idx & 31] = W2[idx];
    for (int idx = tid; idx < 128; idx += blockDim.x)
        sW3[idx >> 2][idx & 3] = W3[idx];
    if (tid < 32) { sB1[tid] = b1[tid]; sB2[tid] = b2[tid]; }
    if (tid < 16) sB3e[tid >> 2][tid & 3] = b3[tid & 3] + d_eps[tid];
    if (tid < 4) {
        sCond[tid] = (mask[tid] == 1) | (mask[4 + tid] == 1) |
                     (mask[8 + tid] == 1) | (mask[12 + tid] == 1);
    }
    __syncthreads();

    const int t = blockIdx.x * blockDim.x + tid;
    if (t >= nPairs) return;

    // elem A = 2t, elem B = 2t+1
    const float4* zp = (const float4*)z + (size_t)t * 8;
    float4* op = (float4*)out + (size_t)t * 8;
    const ulonglong2* b1q = (const ulonglong2*)sB1;  // 128-bit bias init
    const ulonglong2* b2q = (const ulonglong2*)sB2;

#pragma unroll 1   // one column body at a time (I$)
    for (int i = 0; i < 4; i++) {
        if (sCond[i]) {
            // Reload z for this body (L1 hits after first touch).
            float xA[16], xB[16];
#pragma unroll
            for (int r = 0; r < 4; r++) {
                float4 a = ldg128v(zp + r), b = ldg128v(zp + 4 + r);
                xA[r * 4 + 0] = a.x; xA[r * 4 + 1] = a.y;
                xA[r * 4 + 2] = a.z; xA[r * 4 + 3] = a.w;
                xB[r * 4 + 0] = b.x; xB[r * 4 + 1] = b.y;
                xB[r * 4 + 2] = b.z; xB[r * 4 + 3] = b.w;
            }

            // ---- layer 1: 16 -> 32, h1[p] = (h_2p, h_2p+1) ----
            u64 h1A[16], h1B[16];
#pragma unroll
            for (int q = 0; q < 8; q++) {
                ulonglong2 b = b1q[q];
                h1A[2 * q] = b.x; h1A[2 * q + 1] = b.y;
                h1B[2 * q] = b.x; h1B[2 * q + 1] = b.y;
            }
#pragma unroll
            for (int k = 0; k < 16; k++) {
                u64 xa = dup2(xA[k]), xb = dup2(xB[k]);
                const ulonglong2* wr = (const ulonglong2*)sW1[i][k];
#pragma unroll
                for (int q = 0; q < 8; q++) {
                    ulonglong2 w = wr[q];
                    h1A[2 * q]     = fma2(xa, w.x, h1A[2 * q]);
                    h1A[2 * q + 1] = fma2(xa, w.y, h1A[2 * q + 1]);
                    h1B[2 * q]     = fma2(xb, w.x, h1B[2 * q]);
                    h1B[2 * q + 1] = fma2(xb, w.y, h1B[2 * q + 1]);
                }
            }
            // relu + unpack to scalars (x is dead from here on)
            float hA[32], hB[32];
#pragma unroll
            for (int p = 0; p < 16; p++) {
                float la, ha, lb, hb;
                upk2(h1A[p], la, ha); upk2(h1B[p], lb, hb);
                hA[2 * p] = fmaxf(la, 0.0f); hA[2 * p + 1] = fmaxf(ha, 0.0f);
                hB[2 * p] = fmaxf(lb, 0.0f); hB[2 * p + 1] = fmaxf(hb, 0.0f);
            }

            // ---- layer 2: 32 -> 32 ----
            u64 h2A[16], h2B[16];
#pragma unroll
            for (int q = 0; q < 8; q++) {
                ulonglong2 b = b2q[q];
                h2A[2 * q] = b.x; h2A[2 * q + 1] = b.y;
                h2B[2 * q] = b.x; h2B[2 * q + 1] = b.y;
            }
#pragma unroll
            for (int k = 0; k < 32; k++) {
                u64 aa = dup2(hA[k]), ab = dup2(hB[k]);
                const ulonglong2* wr = (const ulonglong2*)sW2[k];
#pragma unroll
                for (int q = 0; q < 8; q++) {
                    ulonglong2 w = wr[q];
                    h2A[2 * q]     = fma2(aa, w.x, h2A[2 * q]);
                    h2A[2 * q + 1] = fma2(aa, w.y, h2A[2 * q + 1]);
                    h2B[2 * q]     = fma2(ab, w.x, h2B[2 * q]);
                    h2B[2 * q + 1] = fma2(ab, w.y, h2B[2 * q + 1]);
                }
            }
#pragma unroll
            for (int p = 0; p < 16; p++) {
                float la, ha, lb, hb;
                upk2(h2A[p], la, ha); upk2(h2B[p], lb, hb);
                hA[2 * p] = fmaxf(la, 0.0f); hA[2 * p + 1] = fmaxf(ha, 0.0f);
                hB[2 * p] = fmaxf(lb, 0.0f); hB[2 * p + 1] = fmaxf(hb, 0.0f);
            }

            // ---- layer 3: 32 -> 4 (+ bias + eps) ----
            const ulonglong2* b3q = (const ulonglong2*)sB3e[i];
            ulonglong2 b3v = b3q[0];
            u64 oA0 = b3v.x, oA1 = b3v.y, oB0 = b3v.x, oB1 = b3v.y;
#pragma unroll
            for (int k = 0; k < 32; k++) {
                u64 aa = dup2(hA[k]), ab = dup2(hB[k]);
                ulonglong2 w = *(const ulonglong2*)sW3[k];
                oA0 = fma2(aa, w.x, oA0);
                oA1 = fma2(aa, w.y, oA1);
                oB0 = fma2(ab, w.x, oB0);
                oB1 = fma2(ab, w.y, oB1);
            }
            float a0, a1, a2, a3, c0, c1, c2, c3;
            upk2(oA0, a0, a1); upk2(oA1, a2, a3);
            upk2(oB0, c0, c1); upk2(oB1, c2, c3);
            op[i]     = make_float4(a0, a1, a2, a3);
            op[4 + i] = make_float4(c0, c1, c2, c3);
        } else {
            // passthrough: out[b, i, :] = z[b, i, :] (fresh load, L1 hit)
            op[i]     = ldg128v(zp + i);
            op[4 + i] = ldg128v(zp + 4 + i);
        }
    }
}

extern "C" void kernel_launch(void* const* d_in, const int* in_sizes, int n_in,
                              void* d_out, int out_size) {
    // metadata order: z, z_int, W1, b1, W2, b2, W3, b3, mask, I
    const float* z  = (const float*)d_in[0];
    const float* W1 = (const float*)d_in[2];
    const float* b1 = (const float*)d_in[3];
    const float* W2 = (const float*)d_in[4];
    const float* b2 = (const float*)d_in[5];
    const float* W3 = (const float*)d_in[6];
    const float* b3 = (const float*)d_in[7];
    const int* mask = (const int*)d_in[8];
    float* out = (float*)d_out;

    int B = in_sizes[0] / 16;   // z is [B, 4, 4]
    int nPairs = B / 2;
    eps_kernel<<<1, 16>>>();
    const int threads = 128;
    int blocks = (nPairs + threads - 1) / threads;
    scm_kernel<<<blocks, threads>>>(z, W1, b1, W2, b2, W3, b3, mask, out, nPairs);
}

// round 17
// speedup vs baseline: 1.1550x; 1.0845x over previous
#include <cuda_runtime.h>
#include <cstdint>

typedef unsigned long long u64;

// W2/W3 live in constant memory: warp-uniform, compile-time addresses ->
// LDCU on the uniform port, off the L1/smem crossbar (the R13 bottleneck).
__constant__ __align__(16) float cW2[32][32];
__constant__ __align__(16) float cW3[32][4];

// eps = jax.random.normal(jax.random.key(42), (4,4)) replicated on device
// (threefry2x32, partitionable path: bits = x0 ^ x1 of threefry(key,(0,idx))).
__device__ float d_eps[16];

__device__ __forceinline__ unsigned rotl32(unsigned x, int r) {
    return (x << r) | (x >> (32 - r));
}

__global__ void eps_kernel() {
    int i = threadIdx.x;
    if (i >= 16) return;
    const unsigned k0 = 0u, k1 = 42u;
    const unsigned k2 = k0 ^ k1 ^ 0x1BD11BDAu;
    unsigned x0 = 0u + k0;           // counts_hi = 0 (idx < 2^32)
    unsigned x1 = (unsigned)i + k1;  // counts_lo = flat index
#define TF4(rA, rB, rC, rD)                              \
    x0 += x1; x1 = rotl32(x1, rA); x1 ^= x0;             \
    x0 += x1; x1 = rotl32(x1, rB); x1 ^= x0;             \
    x0 += x1; x1 = rotl32(x1, rC); x1 ^= x0;             \
    x0 += x1; x1 = rotl32(x1, rD); x1 ^= x0;
    TF4(13, 15, 26, 6)  x0 += k1; x1 += k2 + 1u;
    TF4(17, 29, 16, 24) x0 += k2; x1 += k0 + 2u;
    TF4(13, 15, 26, 6)  x0 += k0; x1 += k1 + 3u;
    TF4(17, 29, 16, 24) x0 += k1; x1 += k2 + 4u;
    TF4(13, 15, 26, 6)  x0 += k2; x1 += k0 + 5u;
#undef TF4
    unsigned bits = x0 ^ x1;
    float f = __uint_as_float((bits >> 9) | 0x3f800000u) - 1.0f;
    const float lo = -0.99999994f;
    float u = f * (1.0f - lo) + lo;
    u = fmaxf(lo, u);
    d_eps[i] = 1.41421356f * erfinvf(u);
}

// ---- packed f32x2 helpers ----
__device__ __forceinline__ void upk2(u64 v, float& a, float& b) {
    asm("mov.b64 {%0, %1}, %2;" : "=f"(a), "=f"(b) : "l"(v));
}
__device__ __forceinline__ u64 fma2(u64 a, u64 b, u64 c) {
    u64 r; asm("fma.rn.f32x2 %0, %1, %2, %3;" : "=l"(r) : "l"(a), "l"(b), "l"(c));
    return r;
}
__device__ __forceinline__ u64 dup2(float v) {
    u64 r; asm("mov.b64 %0, {%1, %1};" : "=l"(r) : "f"(v)); return r;
}
// Volatile vector load: blocks ptxas from CSE-hoisting z reloads out of the
// column loop (which would re-extend x liveness and respill).
__device__ __forceinline__ float4 ldg128v(const float4* p) {
    float4 v;
    asm volatile("ld.global.v4.f32 {%0,%1,%2,%3}, [%4];"
                 : "=f"(v.x), "=f"(v.y), "=f"(v.z), "=f"(v.w) : "l"(p));
    return v;
}

// j-packed scheme: FFMA2 lanes hold adjacent OUTPUT channels (h_2j, h_2j+1).
// Two batch elements per thread share every weight fetch. W1 (mask-scaled at
// runtime) stays in smem; W2/W3 come from __constant__ (uniform port).
__global__ __launch_bounds__(128, 3) void scm_kernel(
    const float* __restrict__ z,
    const float* __restrict__ W1, const float* __restrict__ b1,
    const float* __restrict__ b2, const float* __restrict__ b3,
    const int* __restrict__ mask,
    float* __restrict__ out, int nPairs)
{
    __shared__ __align__(16) float sW1[4][16][32];  // pre-masked per column i
    __shared__ __align__(16) float sB1[32], sB2[32], sB3e[4][4];
    __shared__ int sCond[4];

    const int tid = threadIdx.x;
    for (int idx = tid; idx < 4 * 16 * 32; idx += blockDim.x) {
        int i = idx >> 9, rem = idx & 511, k = rem >> 5, j = rem & 31;
        // masked[i,b,l,f] = z[b,l,f] * mask[f,i], k = l*4+f -> f = k&3
        float m = (float)mask[(k & 3) * 4 + i];
        sW1[i][k][j] = W1[k * 32 + j] * m;
    }
    if (tid < 32) { sB1[tid] = b1[tid]; sB2[tid] = b2[tid]; }
    if (tid < 16) sB3e[tid >> 2][tid & 3] = b3[tid & 3] + d_eps[tid];
    if (tid < 4) {
        sCond[tid] = (mask[tid] == 1) | (mask[4 + tid] == 1) |
                     (mask[8 + tid] == 1) | (mask[12 + tid] == 1);
    }
    __syncthreads();

    const int t = blockIdx.x * blockDim.x + tid;
    if (t >= nPairs) return;

    // elem A = 2t, elem B = 2t+1
    const float4* zp = (const float4*)z + (size_t)t * 8;
    float4* op = (float4*)out + (size_t)t * 8;
    const ulonglong2* b1q = (const ulonglong2*)sB1;  // 128-bit bias init
    const ulonglong2* b2q = (const ulonglong2*)sB2;

#pragma unroll 1   // one column body at a time (I$)
    for (int i = 0; i < 4; i++) {
        if (sCond[i]) {
            // Reload z for this body (L1 hits after first touch).
            float xA[16], xB[16];
#pragma unroll
            for (int r = 0; r < 4; r++) {
                float4 a = ldg128v(zp + r), b = ldg128v(zp + 4 + r);
                xA[r * 4 + 0] = a.x; xA[r * 4 + 1] = a.y;
                xA[r * 4 + 2] = a.z; xA[r * 4 + 3] = a.w;
                xB[r * 4 + 0] = b.x; xB[r * 4 + 1] = b.y;
                xB[r * 4 + 2] = b.z; xB[r * 4 + 3] = b.w;
            }

            // ---- layer 1: 16 -> 32 (weights from smem), h1[p]=(h_2p,h_2p+1)
            u64 h1A[16], h1B[16];
#pragma unroll
            for (int q = 0; q < 8; q++) {
                ulonglong2 b = b1q[q];
                h1A[2 * q] = b.x; h1A[2 * q + 1] = b.y;
                h1B[2 * q] = b.x; h1B[2 * q + 1] = b.y;
            }
#pragma unroll
            for (int k = 0; k < 16; k++) {
                u64 xa = dup2(xA[k]), xb = dup2(xB[k]);
                const ulonglong2* wr = (const ulonglong2*)sW1[i][k];
#pragma unroll
                for (int q = 0; q < 8; q++) {
                    ulonglong2 w = wr[q];
                    h1A[2 * q]     = fma2(xa, w.x, h1A[2 * q]);
                    h1A[2 * q + 1] = fma2(xa, w.y, h1A[2 * q + 1]);
                    h1B[2 * q]     = fma2(xb, w.x, h1B[2 * q]);
                    h1B[2 * q + 1] = fma2(xb, w.y, h1B[2 * q + 1]);
                }
            }
            // relu + unpack to scalars (x dead from here)
            float hA[32], hB[32];
#pragma unroll
            for (int p = 0; p < 16; p++) {
                float la, ha, lb, hb;
                upk2(h1A[p], la, ha); upk2(h1B[p], lb, hb);
                hA[2 * p] = fmaxf(la, 0.0f); hA[2 * p + 1] = fmaxf(ha, 0.0f);
                hB[2 * p] = fmaxf(lb, 0.0f); hB[2 * p + 1] = fmaxf(hb, 0.0f);
            }

            // ---- layer 2: 32 -> 32 (weights from __constant__) ----
            u64 h2A[16], h2B[16];
#pragma unroll
            for (int q = 0; q < 8; q++) {
                ulonglong2 b = b2q[q];
                h2A[2 * q] = b.x; h2A[2 * q + 1] = b.y;
                h2B[2 * q] = b.x; h2B[2 * q + 1] = b.y;
            }
#pragma unroll
            for (int k = 0; k < 32; k++) {
                u64 aa = dup2(hA[k]), ab = dup2(hB[k]);
                const ulonglong2* wr = (const ulonglong2*)cW2[k];
#pragma unroll
                for (int q = 0; q < 8; q++) {
                    ulonglong2 w = wr[q];
                    h2A[2 * q]     = fma2(aa, w.x, h2A[2 * q]);
                    h2A[2 * q + 1] = fma2(aa, w.y, h2A[2 * q + 1]);
                    h2B[2 * q]     = fma2(ab, w.x, h2B[2 * q]);
                    h2B[2 * q + 1] = fma2(ab, w.y, h2B[2 * q + 1]);
                }
            }
#pragma unroll
            for (int p = 0; p < 16; p++) {
                float la, ha, lb, hb;
                upk2(h2A[p], la, ha); upk2(h2B[p], lb, hb);
                hA[2 * p] = fmaxf(la, 0.0f); hA[2 * p + 1] = fmaxf(ha, 0.0f);
                hB[2 * p] = fmaxf(lb, 0.0f); hB[2 * p + 1] = fmaxf(hb, 0.0f);
            }

            // ---- layer 3: 32 -> 4 (+ bias + eps), weights from __constant__
            const ulonglong2* b3q = (const ulonglong2*)sB3e[i];
            ulonglong2 b3v = b3q[0];
            u64 oA0 = b3v.x, oA1 = b3v.y, oB0 = b3v.x, oB1 = b3v.y;
#pragma unroll
            for (int k = 0; k < 32; k++) {
                u64 aa = dup2(hA[k]), ab = dup2(hB[k]);
                ulonglong2 w = *(const ulonglong2*)cW3[k];
                oA0 = fma2(aa, w.x, oA0);
                oA1 = fma2(aa, w.y, oA1);
                oB0 = fma2(ab, w.x, oB0);
                oB1 = fma2(ab, w.y, oB1);
            }
            float a0, a1, a2, a3, c0, c1, c2, c3;
            upk2(oA0, a0, a1); upk2(oA1, a2, a3);
            upk2(oB0, c0, c1); upk2(oB1, c2, c3);
            op[i]     = make_float4(a0, a1, a2, a3);
            op[4 + i] = make_float4(c0, c1, c2, c3);
        } else {
            // passthrough: out[b, i, :] = z[b, i, :] (fresh load, L1 hit)
            op[i]     = ldg128v(zp + i);
            op[4 + i] = ldg128v(zp + 4 + i);
        }
    }
}

extern "C" void kernel_launch(void* const* d_in, const int* in_sizes, int n_in,
                              void* d_out, int out_size) {
    // metadata order: z, z_int, W1, b1, W2, b2, W3, b3, mask, I
    const float* z  = (const float*)d_in[0];
    const float* W1 = (const float*)d_in[2];
    const float* b1 = (const float*)d_in[3];
    const float* W2 = (const float*)d_in[4];
    const float* b2 = (const float*)d_in[5];
    const float* W3 = (const float*)d_in[6];
    const float* b3 = (const float*)d_in[7];
    const int* mask = (const int*)d_in[8];
    float* out = (float*)d_out;

    // Stage W2/W3 into constant memory (capturable D2D memcpy nodes).
    cudaMemcpyToSymbolAsync(cW2, W2, 32 * 32 * sizeof(float), 0,
                            cudaMemcpyDeviceToDevice, 0);
    cudaMemcpyToSymbolAsync(cW3, W3, 32 * 4 * sizeof(float), 0,
                            cudaMemcpyDeviceToDevice, 0);

    int B = in_sizes[0] / 16;   // z is [B, 4, 4]
    int nPairs = B / 2;
    eps_kernel<<<1, 16>>>();
    const int threads = 128;
    int blocks = (nPairs + threads - 1) / threads;
    scm_kernel<<<blocks, threads>>>(z, W1, b1, b2, b3, mask, out, nPairs);
}